// round 1
// baseline (speedup 1.0000x reference)
#include <cuda_runtime.h>
#include <cuda_bf16.h>
#include <mma.h>

using namespace nvcuda;
typedef __nv_bfloat16 bf16;

#define TOKENS 8192
#define DM 1024
#define NH 16
#define SD 64
#define NS 1024

// ---------------- scratch (static __device__, no allocation) ----------------
__device__ __align__(16) bf16 g_xh[TOKENS * DM];     // x_norm hi
__device__ __align__(16) bf16 g_xl[TOKENS * DM];     // x_norm lo
__device__ __align__(16) bf16 g_qh[TOKENS * DM];     // q hi
__device__ __align__(16) bf16 g_ql[TOKENS * DM];     // q lo
__device__ __align__(16) bf16 g_read[TOKENS * DM];   // routed read (bf16)
__device__ __align__(16) bf16 g_wqh[DM * DM];        // q_w hi
__device__ __align__(16) bf16 g_wql[DM * DM];        // q_w lo
__device__ __align__(16) bf16 g_wo[DM * DM];         // out_w (plain bf16)
__device__ __align__(16) bf16 g_sig[NH * NS * SD];   // ternarized signatures

// ---------------- convert weights / ternarize signatures --------------------
__global__ void __launch_bounds__(256) convert_kernel(const float* __restrict__ qw,
                                                      const float* __restrict__ ow,
                                                      const float* __restrict__ sig) {
    int i = blockIdx.x * 256 + threadIdx.x;
    const int N = DM * DM;
    if (i < N) {
        float w = qw[i];
        bf16 h = __float2bfloat16(w);
        g_wqh[i] = h;
        g_wql[i] = __float2bfloat16(w - __bfloat162float(h));
    } else if (i < 2 * N) {
        g_wo[i - N] = __float2bfloat16(ow[i - N]);
    } else if (i < 2 * N + NH * NS * SD) {
        float s = sig[i - 2 * N];
        float t = (s > 0.3f) ? 1.0f : ((s < -0.3f) ? -1.0f : 0.0f);
        g_sig[i - 2 * N] = __float2bfloat16(t);
    }
}

// ---------------- layernorm with hi/lo split output -------------------------
__global__ void __launch_bounds__(256) ln_kernel(const float* __restrict__ x,
                                                 const float* __restrict__ gamma,
                                                 const float* __restrict__ beta) {
    int m = blockIdx.x;
    int tid = threadIdx.x;
    const float4 v = reinterpret_cast<const float4*>(x + (size_t)m * DM)[tid];
    float s = v.x + v.y + v.z + v.w;
    float q = v.x * v.x + v.y * v.y + v.z * v.z + v.w * v.w;
#pragma unroll
    for (int o = 16; o; o >>= 1) {
        s += __shfl_xor_sync(0xffffffffu, s, o);
        q += __shfl_xor_sync(0xffffffffu, q, o);
    }
    __shared__ float ss[8], qq[8];
    int w = tid >> 5;
    if ((tid & 31) == 0) { ss[w] = s; qq[w] = q; }
    __syncthreads();
    if (tid == 0) {
        float S = 0.f, Q = 0.f;
        for (int i = 0; i < 8; i++) { S += ss[i]; Q += qq[i]; }
        ss[0] = S; qq[0] = Q;
    }
    __syncthreads();
    float mean = ss[0] * (1.0f / DM);
    float var = qq[0] * (1.0f / DM) - mean * mean;
    float r = rsqrtf(var + 1e-5f);
    const float4 g = reinterpret_cast<const float4*>(gamma)[tid];
    const float4 b = reinterpret_cast<const float4*>(beta)[tid];
    float o0 = (v.x - mean) * r * g.x + b.x;
    float o1 = (v.y - mean) * r * g.y + b.y;
    float o2 = (v.z - mean) * r * g.z + b.z;
    float o3 = (v.w - mean) * r * g.w + b.w;
    size_t base = (size_t)m * DM + tid * 4;
    float oo[4] = {o0, o1, o2, o3};
#pragma unroll
    for (int i = 0; i < 4; i++) {
        bf16 h = __float2bfloat16(oo[i]);
        g_xh[base + i] = h;
        g_xl[base + i] = __float2bfloat16(oo[i] - __bfloat162float(h));
    }
}

// ---------------- split-bf16 q projection: q = xn @ q_w^T + q_b -------------
// C[m,n] = sum_k A[m,k] * W[n,k];  A = hi+lo, W = hi+lo, 3 products kept.
__global__ void __launch_bounds__(256) gemm_qproj(const float* __restrict__ qb) {
    __shared__ __align__(16) bf16 Ah[128 * 40];
    __shared__ __align__(16) bf16 Al[128 * 40];
    __shared__ __align__(16) bf16 Wh[64 * 40];
    __shared__ __align__(16) bf16 Wl[64 * 40];
    __shared__ __align__(16) float Cs[8 * 16 * 20];

    int tid = threadIdx.x, warp = tid >> 5, lane = tid & 31;
    int m0 = blockIdx.y * 128, n0 = blockIdx.x * 64;
    int wm = warp & 3, wn = warp >> 2;

    wmma::fragment<wmma::accumulator, 16, 16, 16, float> acc[2][2];
#pragma unroll
    for (int i = 0; i < 2; i++)
#pragma unroll
        for (int j = 0; j < 2; j++) wmma::fill_fragment(acc[i][j], 0.0f);

    int rA = tid >> 2, cv = tid & 3;
    for (int k0 = 0; k0 < DM; k0 += 32) {
        size_t a0 = (size_t)(m0 + rA) * DM + k0 + cv * 8;
        size_t a1 = (size_t)(m0 + rA + 64) * DM + k0 + cv * 8;
        ((uint4*)(Ah + rA * 40))[cv] = *(const uint4*)(g_xh + a0);
        ((uint4*)(Ah + (rA + 64) * 40))[cv] = *(const uint4*)(g_xh + a1);
        ((uint4*)(Al + rA * 40))[cv] = *(const uint4*)(g_xl + a0);
        ((uint4*)(Al + (rA + 64) * 40))[cv] = *(const uint4*)(g_xl + a1);
        size_t w0 = (size_t)(n0 + rA) * DM + k0 + cv * 8;
        ((uint4*)(Wh + rA * 40))[cv] = *(const uint4*)(g_wqh + w0);
        ((uint4*)(Wl + rA * 40))[cv] = *(const uint4*)(g_wql + w0);
        __syncthreads();
#pragma unroll
        for (int ks = 0; ks < 2; ks++) {
            wmma::fragment<wmma::matrix_a, 16, 16, 16, bf16, wmma::row_major> ah[2], al[2];
            wmma::fragment<wmma::matrix_b, 16, 16, 16, bf16, wmma::col_major> bh[2], bl[2];
#pragma unroll
            for (int i = 0; i < 2; i++) {
                wmma::load_matrix_sync(ah[i], Ah + (wm * 32 + i * 16) * 40 + ks * 16, 40);
                wmma::load_matrix_sync(al[i], Al + (wm * 32 + i * 16) * 40 + ks * 16, 40);
            }
#pragma unroll
            for (int j = 0; j < 2; j++) {
                wmma::load_matrix_sync(bh[j], Wh + (wn * 32 + j * 16) * 40 + ks * 16, 40);
                wmma::load_matrix_sync(bl[j], Wl + (wn * 32 + j * 16) * 40 + ks * 16, 40);
            }
#pragma unroll
            for (int i = 0; i < 2; i++)
#pragma unroll
                for (int j = 0; j < 2; j++) {
                    wmma::mma_sync(acc[i][j], ah[i], bh[j], acc[i][j]);
                    wmma::mma_sync(acc[i][j], ah[i], bl[j], acc[i][j]);
                    wmma::mma_sync(acc[i][j], al[i], bh[j], acc[i][j]);
                }
        }
        __syncthreads();
    }
    // epilogue: fp32 -> (hi, lo) bf16 pair
    float* cs = Cs + warp * (16 * 20);
#pragma unroll
    for (int i = 0; i < 2; i++)
#pragma unroll
        for (int j = 0; j < 2; j++) {
            wmma::store_matrix_sync(cs, acc[i][j], 20, wmma::mem_row_major);
            __syncwarp();
            int mb = m0 + wm * 32 + i * 16, nb = n0 + wn * 32 + j * 16;
#pragma unroll
            for (int t = 0; t < 8; t++) {
                int e = t * 32 + lane;
                int r = e >> 4, c = e & 15;
                float val = cs[r * 20 + c] + qb[nb + c];
                bf16 h = __float2bfloat16(val);
                size_t o = (size_t)(mb + r) * DM + nb + c;
                g_qh[o] = h;
                g_ql[o] = __float2bfloat16(val - __bfloat162float(h));
            }
            __syncwarp();
        }
}

// ---------------- fused scores + top-2 + softmax + gather -------------------
// grid (128 token-tiles, 16 heads), 256 threads. 64-token tile, 64-slot chunks.
__global__ void __launch_bounds__(256) scores_kernel(const float* __restrict__ vals,
                                                     const float* __restrict__ temp) {
    __shared__ __align__(16) bf16 Qh[64 * 80];
    __shared__ __align__(16) bf16 Ql[64 * 80];
    __shared__ __align__(16) float Sc[64 * 68];   // also aliased as bf16 Ss[64*80]
    __shared__ float w1s[64], w2s[64];
    __shared__ int i1s[64], i2s[64];
    bf16* Ss = (bf16*)Sc;

    int tid = threadIdx.x, warp = tid >> 5;
    int m0 = blockIdx.x * 64;
    int h = blockIdx.y;

    // load Q tile (hi + lo): 64 tokens x 64 dims
    {
        int row = tid >> 3, v = tid & 7;
        size_t b1 = (size_t)(m0 + row) * DM + h * SD + v * 8;
        size_t b2 = (size_t)(m0 + row + 32) * DM + h * SD + v * 8;
        ((uint4*)(Qh + row * 80))[v] = *(const uint4*)(g_qh + b1);
        ((uint4*)(Qh + (row + 32) * 80))[v] = *(const uint4*)(g_qh + b2);
        ((uint4*)(Ql + row * 80))[v] = *(const uint4*)(g_ql + b1);
        ((uint4*)(Ql + (row + 32) * 80))[v] = *(const uint4*)(g_ql + b2);
    }

    float v1 = -1e30f, v2 = -1e30f;
    int i1 = 0, i2 = 0;
    int tm = warp >> 1;
    int tcb = (warp & 1) * 2;

    for (int c = 0; c < 16; c++) {
        __syncthreads();  // prev Sc scan done / Q loads done
        {   // load 64-slot signature chunk into Ss (aliased onto Sc)
            int row = tid >> 3, v = tid & 7;
            size_t s1 = ((size_t)h * NS + c * 64 + row) * SD + v * 8;
            ((uint4*)(Ss + row * 80))[v] = *(const uint4*)(g_sig + s1);
            ((uint4*)(Ss + (row + 32) * 80))[v] = *(const uint4*)(g_sig + s1 + 32 * SD);
        }
        __syncthreads();

        wmma::fragment<wmma::accumulator, 16, 16, 16, float> acc[2];
        wmma::fill_fragment(acc[0], 0.0f);
        wmma::fill_fragment(acc[1], 0.0f);
#pragma unroll
        for (int k = 0; k < 4; k++) {
            wmma::fragment<wmma::matrix_a, 16, 16, 16, bf16, wmma::row_major> ah, al;
            wmma::load_matrix_sync(ah, Qh + tm * 16 * 80 + k * 16, 80);
            wmma::load_matrix_sync(al, Ql + tm * 16 * 80 + k * 16, 80);
#pragma unroll
            for (int j = 0; j < 2; j++) {
                wmma::fragment<wmma::matrix_b, 16, 16, 16, bf16, wmma::col_major> bb;
                wmma::load_matrix_sync(bb, Ss + (tcb + j) * 16 * 80 + k * 16, 80);
                wmma::mma_sync(acc[j], ah, bb, acc[j]);
                wmma::mma_sync(acc[j], al, bb, acc[j]);
            }
        }
        __syncthreads();  // all Ss reads done before Sc overwrite
        wmma::store_matrix_sync(Sc + tm * 16 * 68 + (tcb + 0) * 16, acc[0], 68, wmma::mem_row_major);
        wmma::store_matrix_sync(Sc + tm * 16 * 68 + (tcb + 1) * 16, acc[1], 68, wmma::mem_row_major);
        __syncthreads();

        if (tid < 64) {   // running top-2 (ascending index scan => lowest-index tie-break)
            int base = c * 64;
#pragma unroll 4
            for (int cc = 0; cc < 64; cc++) {
                float s = Sc[tid * 68 + cc];
                if (s > v1) { v2 = v1; i2 = i1; v1 = s; i1 = base + cc; }
                else if (s > v2) { v2 = s; i2 = base + cc; }
            }
        }
    }
    __syncthreads();

    if (tid < 64) {
        float t = temp[0];
        float inv = 1.0f / (t * 8.0f);           // 1/(temperature*sqrt(64))
        float e = expf((v2 - v1) * inv);
        float w1 = 1.0f / (1.0f + e);
        w1s[tid] = w1;
        w2s[tid] = 1.0f - w1;
        i1s[tid] = i1;
        i2s[tid] = i2;
    }
    __syncthreads();

    {   // gather slot values, blend, write bf16 read
        int tt = tid >> 2, p = tid & 3;
        const float* V = vals + (size_t)h * NS * SD;
        const float4* r1 = (const float4*)(V + (size_t)i1s[tt] * SD);
        const float4* r2 = (const float4*)(V + (size_t)i2s[tt] * SD);
        float a = w1s[tt], b = w2s[tt];
        bf16* dst = g_read + (size_t)(m0 + tt) * DM + h * SD + p * 16;
#pragma unroll
        for (int j = 0; j < 4; j++) {
            float4 xa = r1[p * 4 + j], xb = r2[p * 4 + j];
            float f0 = a * xa.x + b * xb.x;
            float f1 = a * xa.y + b * xb.y;
            float f2 = a * xa.z + b * xb.z;
            float f3 = a * xa.w + b * xb.w;
            ((__nv_bfloat162*)(dst + j * 4))[0] = __floats2bfloat162_rn(f0, f1);
            ((__nv_bfloat162*)(dst + j * 4))[1] = __floats2bfloat162_rn(f2, f3);
        }
    }
}

// ---------------- out projection: out = read @ out_w^T + out_b + x ----------
__global__ void __launch_bounds__(256) gemm_out(const float* __restrict__ ob,
                                                const float* __restrict__ x,
                                                float* __restrict__ out) {
    __shared__ __align__(16) bf16 As[128 * 40];
    __shared__ __align__(16) bf16 Ws[64 * 40];
    __shared__ __align__(16) float Cs[8 * 16 * 20];

    int tid = threadIdx.x, warp = tid >> 5, lane = tid & 31;
    int m0 = blockIdx.y * 128, n0 = blockIdx.x * 64;
    int wm = warp & 3, wn = warp >> 2;

    wmma::fragment<wmma::accumulator, 16, 16, 16, float> acc[2][2];
#pragma unroll
    for (int i = 0; i < 2; i++)
#pragma unroll
        for (int j = 0; j < 2; j++) wmma::fill_fragment(acc[i][j], 0.0f);

    int rA = tid >> 2, cv = tid & 3;
    for (int k0 = 0; k0 < DM; k0 += 32) {
        size_t a0 = (size_t)(m0 + rA) * DM + k0 + cv * 8;
        size_t a1 = (size_t)(m0 + rA + 64) * DM + k0 + cv * 8;
        ((uint4*)(As + rA * 40))[cv] = *(const uint4*)(g_read + a0);
        ((uint4*)(As + (rA + 64) * 40))[cv] = *(const uint4*)(g_read + a1);
        size_t w0 = (size_t)(n0 + rA) * DM + k0 + cv * 8;
        ((uint4*)(Ws + rA * 40))[cv] = *(const uint4*)(g_wo + w0);
        __syncthreads();
#pragma unroll
        for (int ks = 0; ks < 2; ks++) {
            wmma::fragment<wmma::matrix_a, 16, 16, 16, bf16, wmma::row_major> af[2];
            wmma::fragment<wmma::matrix_b, 16, 16, 16, bf16, wmma::col_major> bf_[2];
#pragma unroll
            for (int i = 0; i < 2; i++)
                wmma::load_matrix_sync(af[i], As + (wm * 32 + i * 16) * 40 + ks * 16, 40);
#pragma unroll
            for (int j = 0; j < 2; j++)
                wmma::load_matrix_sync(bf_[j], Ws + (wn * 32 + j * 16) * 40 + ks * 16, 40);
#pragma unroll
            for (int i = 0; i < 2; i++)
#pragma unroll
                for (int j = 0; j < 2; j++)
                    wmma::mma_sync(acc[i][j], af[i], bf_[j], acc[i][j]);
        }
        __syncthreads();
    }
    float* cs = Cs + warp * (16 * 20);
#pragma unroll
    for (int i = 0; i < 2; i++)
#pragma unroll
        for (int j = 0; j < 2; j++) {
            wmma::store_matrix_sync(cs, acc[i][j], 20, wmma::mem_row_major);
            __syncwarp();
            int mb = m0 + wm * 32 + i * 16, nb = n0 + wn * 32 + j * 16;
#pragma unroll
            for (int t = 0; t < 8; t++) {
                int e = t * 32 + lane;
                int r = e >> 4, c = e & 15;
                size_t o = (size_t)(mb + r) * DM + nb + c;
                out[o] = cs[r * 20 + c] + ob[nb + c] + x[o];
            }
            __syncwarp();
        }
}

// ---------------- launch ----------------------------------------------------
extern "C" void kernel_launch(void* const* d_in, const int* in_sizes, int n_in,
                              void* d_out, int out_size) {
    const float* x = (const float*)d_in[0];
    const float* gamma = (const float*)d_in[1];
    const float* beta = (const float*)d_in[2];
    const float* qw = (const float*)d_in[3];
    const float* qb = (const float*)d_in[4];
    const float* sig = (const float*)d_in[5];
    const float* vals = (const float*)d_in[6];
    const float* ow = (const float*)d_in[7];
    const float* ob = (const float*)d_in[8];
    const float* temp = (const float*)d_in[9];
    float* out = (float*)d_out;

    convert_kernel<<<(3 * DM * DM) / 256, 256>>>(qw, ow, sig);
    ln_kernel<<<TOKENS, 256>>>(x, gamma, beta);
    gemm_qproj<<<dim3(DM / 64, TOKENS / 128), 256>>>(qb);
    scores_kernel<<<dim3(TOKENS / 64, NH), 256>>>(vals, temp);
    gemm_out<<<dim3(DM / 64, TOKENS / 128), 256>>>(ob, x, out);
}

// round 2
// speedup vs baseline: 1.0027x; 1.0027x over previous
#include <cuda_runtime.h>
#include <cuda_bf16.h>
#include <mma.h>

using namespace nvcuda;
typedef __nv_bfloat16 bf16;

#define TOKENS 8192
#define DM 1024
#define NH 16
#define SD 64
#define NS 1024

// ---------------- scratch (static __device__, no allocation) ----------------
__device__ __align__(16) bf16 g_xh[TOKENS * DM];     // x_norm hi
__device__ __align__(16) bf16 g_xl[TOKENS * DM];     // x_norm lo
__device__ __align__(16) bf16 g_qh[TOKENS * DM];     // q hi
__device__ __align__(16) bf16 g_ql[TOKENS * DM];     // q lo
__device__ __align__(16) bf16 g_read[TOKENS * DM];   // routed read (bf16)
__device__ __align__(16) bf16 g_wqh[DM * DM];        // q_w hi
__device__ __align__(16) bf16 g_wql[DM * DM];        // q_w lo
__device__ __align__(16) bf16 g_wo[DM * DM];         // out_w (plain bf16)
__device__ __align__(16) bf16 g_sig[NH * NS * SD];   // ternarized signatures

// ---------------- convert weights / ternarize signatures --------------------
__global__ void __launch_bounds__(256) convert_kernel(const float* __restrict__ qw,
                                                      const float* __restrict__ ow,
                                                      const float* __restrict__ sig) {
    int i = blockIdx.x * 256 + threadIdx.x;
    const int N = DM * DM;
    if (i < N) {
        float w = qw[i];
        bf16 h = __float2bfloat16(w);
        g_wqh[i] = h;
        g_wql[i] = __float2bfloat16(w - __bfloat162float(h));
    } else if (i < 2 * N) {
        g_wo[i - N] = __float2bfloat16(ow[i - N]);
    } else if (i < 2 * N + NH * NS * SD) {
        float s = sig[i - 2 * N];
        float t = (s > 0.3f) ? 1.0f : ((s < -0.3f) ? -1.0f : 0.0f);
        g_sig[i - 2 * N] = __float2bfloat16(t);
    }
}

// ---------------- layernorm with hi/lo split output -------------------------
__global__ void __launch_bounds__(256) ln_kernel(const float* __restrict__ x,
                                                 const float* __restrict__ gamma,
                                                 const float* __restrict__ beta) {
    int m = blockIdx.x;
    int tid = threadIdx.x;
    const float4 v = reinterpret_cast<const float4*>(x + (size_t)m * DM)[tid];
    float s = v.x + v.y + v.z + v.w;
    float q = v.x * v.x + v.y * v.y + v.z * v.z + v.w * v.w;
#pragma unroll
    for (int o = 16; o; o >>= 1) {
        s += __shfl_xor_sync(0xffffffffu, s, o);
        q += __shfl_xor_sync(0xffffffffu, q, o);
    }
    __shared__ float ss[8], qq[8];
    int w = tid >> 5;
    if ((tid & 31) == 0) { ss[w] = s; qq[w] = q; }
    __syncthreads();
    if (tid == 0) {
        float S = 0.f, Q = 0.f;
        for (int i = 0; i < 8; i++) { S += ss[i]; Q += qq[i]; }
        ss[0] = S; qq[0] = Q;
    }
    __syncthreads();
    float mean = ss[0] * (1.0f / DM);
    float var = qq[0] * (1.0f / DM) - mean * mean;
    float r = rsqrtf(var + 1e-5f);
    const float4 g = reinterpret_cast<const float4*>(gamma)[tid];
    const float4 b = reinterpret_cast<const float4*>(beta)[tid];
    float o0 = (v.x - mean) * r * g.x + b.x;
    float o1 = (v.y - mean) * r * g.y + b.y;
    float o2 = (v.z - mean) * r * g.z + b.z;
    float o3 = (v.w - mean) * r * g.w + b.w;
    size_t base = (size_t)m * DM + tid * 4;
    float oo[4] = {o0, o1, o2, o3};
#pragma unroll
    for (int i = 0; i < 4; i++) {
        bf16 h = __float2bfloat16(oo[i]);
        g_xh[base + i] = h;
        g_xl[base + i] = __float2bfloat16(oo[i] - __bfloat162float(h));
    }
}

// ---------------- split-bf16 q projection: q = xn @ q_w^T + q_b -------------
// C[m,n] = sum_k A[m,k] * W[n,k];  A = hi+lo, W = hi+lo, 3 products kept.
__global__ void __launch_bounds__(256) gemm_qproj(const float* __restrict__ qb) {
    __shared__ __align__(16) bf16 Ah[128 * 40];
    __shared__ __align__(16) bf16 Al[128 * 40];
    __shared__ __align__(16) bf16 Wh[64 * 40];
    __shared__ __align__(16) bf16 Wl[64 * 40];
    __shared__ __align__(16) float Cs[8 * 16 * 20];

    int tid = threadIdx.x, warp = tid >> 5, lane = tid & 31;
    int m0 = blockIdx.y * 128, n0 = blockIdx.x * 64;
    int wm = warp & 3, wn = warp >> 2;

    wmma::fragment<wmma::accumulator, 16, 16, 16, float> acc[2][2];
#pragma unroll
    for (int i = 0; i < 2; i++)
#pragma unroll
        for (int j = 0; j < 2; j++) wmma::fill_fragment(acc[i][j], 0.0f);

    int rA = tid >> 2, cv = tid & 3;
    for (int k0 = 0; k0 < DM; k0 += 32) {
        size_t a0 = (size_t)(m0 + rA) * DM + k0 + cv * 8;
        size_t a1 = (size_t)(m0 + rA + 64) * DM + k0 + cv * 8;
        ((uint4*)(Ah + rA * 40))[cv] = *(const uint4*)(g_xh + a0);
        ((uint4*)(Ah + (rA + 64) * 40))[cv] = *(const uint4*)(g_xh + a1);
        ((uint4*)(Al + rA * 40))[cv] = *(const uint4*)(g_xl + a0);
        ((uint4*)(Al + (rA + 64) * 40))[cv] = *(const uint4*)(g_xl + a1);
        size_t w0 = (size_t)(n0 + rA) * DM + k0 + cv * 8;
        ((uint4*)(Wh + rA * 40))[cv] = *(const uint4*)(g_wqh + w0);
        ((uint4*)(Wl + rA * 40))[cv] = *(const uint4*)(g_wql + w0);
        __syncthreads();
#pragma unroll
        for (int ks = 0; ks < 2; ks++) {
            wmma::fragment<wmma::matrix_a, 16, 16, 16, bf16, wmma::row_major> ah[2], al[2];
            wmma::fragment<wmma::matrix_b, 16, 16, 16, bf16, wmma::col_major> bh[2], bl[2];
#pragma unroll
            for (int i = 0; i < 2; i++) {
                wmma::load_matrix_sync(ah[i], Ah + (wm * 32 + i * 16) * 40 + ks * 16, 40);
                wmma::load_matrix_sync(al[i], Al + (wm * 32 + i * 16) * 40 + ks * 16, 40);
            }
#pragma unroll
            for (int j = 0; j < 2; j++) {
                wmma::load_matrix_sync(bh[j], Wh + (wn * 32 + j * 16) * 40 + ks * 16, 40);
                wmma::load_matrix_sync(bl[j], Wl + (wn * 32 + j * 16) * 40 + ks * 16, 40);
            }
#pragma unroll
            for (int i = 0; i < 2; i++)
#pragma unroll
                for (int j = 0; j < 2; j++) {
                    wmma::mma_sync(acc[i][j], ah[i], bh[j], acc[i][j]);
                    wmma::mma_sync(acc[i][j], ah[i], bl[j], acc[i][j]);
                    wmma::mma_sync(acc[i][j], al[i], bh[j], acc[i][j]);
                }
        }
        __syncthreads();
    }
    // epilogue: fp32 -> (hi, lo) bf16 pair
    float* cs = Cs + warp * (16 * 20);
#pragma unroll
    for (int i = 0; i < 2; i++)
#pragma unroll
        for (int j = 0; j < 2; j++) {
            wmma::store_matrix_sync(cs, acc[i][j], 20, wmma::mem_row_major);
            __syncwarp();
            int mb = m0 + wm * 32 + i * 16, nb = n0 + wn * 32 + j * 16;
#pragma unroll
            for (int t = 0; t < 8; t++) {
                int e = t * 32 + lane;
                int r = e >> 4, c = e & 15;
                float val = cs[r * 20 + c] + qb[nb + c];
                bf16 h = __float2bfloat16(val);
                size_t o = (size_t)(mb + r) * DM + nb + c;
                g_qh[o] = h;
                g_ql[o] = __float2bfloat16(val - __bfloat162float(h));
            }
            __syncwarp();
        }
}

// ---------------- fused scores + top-2 + softmax + gather -------------------
// grid (128 token-tiles, 16 heads), 256 threads. 64-token tile, 64-slot chunks.
__global__ void __launch_bounds__(256) scores_kernel(const float* __restrict__ vals,
                                                     const float* __restrict__ temp) {
    __shared__ __align__(16) bf16 Qh[64 * 80];
    __shared__ __align__(16) bf16 Ql[64 * 80];
    __shared__ __align__(16) float Sc[64 * 68];   // also aliased as bf16 Ss[64*80]
    __shared__ float w1s[64], w2s[64];
    __shared__ int i1s[64], i2s[64];
    bf16* Ss = (bf16*)Sc;

    int tid = threadIdx.x, warp = tid >> 5;
    int m0 = blockIdx.x * 64;
    int h = blockIdx.y;

    // load Q tile (hi + lo): 64 tokens x 64 dims
    {
        int row = tid >> 3, v = tid & 7;
        size_t b1 = (size_t)(m0 + row) * DM + h * SD + v * 8;
        size_t b2 = (size_t)(m0 + row + 32) * DM + h * SD + v * 8;
        ((uint4*)(Qh + row * 80))[v] = *(const uint4*)(g_qh + b1);
        ((uint4*)(Qh + (row + 32) * 80))[v] = *(const uint4*)(g_qh + b2);
        ((uint4*)(Ql + row * 80))[v] = *(const uint4*)(g_ql + b1);
        ((uint4*)(Ql + (row + 32) * 80))[v] = *(const uint4*)(g_ql + b2);
    }

    float v1 = -1e30f, v2 = -1e30f;
    int i1 = 0, i2 = 0;
    int tm = warp >> 1;
    int tcb = (warp & 1) * 2;

    for (int c = 0; c < 16; c++) {
        __syncthreads();  // prev Sc scan done / Q loads done
        {   // load 64-slot signature chunk into Ss (aliased onto Sc)
            int row = tid >> 3, v = tid & 7;
            size_t s1 = ((size_t)h * NS + c * 64 + row) * SD + v * 8;
            ((uint4*)(Ss + row * 80))[v] = *(const uint4*)(g_sig + s1);
            ((uint4*)(Ss + (row + 32) * 80))[v] = *(const uint4*)(g_sig + s1 + 32 * SD);
        }
        __syncthreads();

        wmma::fragment<wmma::accumulator, 16, 16, 16, float> acc[2];
        wmma::fill_fragment(acc[0], 0.0f);
        wmma::fill_fragment(acc[1], 0.0f);
#pragma unroll
        for (int k = 0; k < 4; k++) {
            wmma::fragment<wmma::matrix_a, 16, 16, 16, bf16, wmma::row_major> ah, al;
            wmma::load_matrix_sync(ah, Qh + tm * 16 * 80 + k * 16, 80);
            wmma::load_matrix_sync(al, Ql + tm * 16 * 80 + k * 16, 80);
#pragma unroll
            for (int j = 0; j < 2; j++) {
                wmma::fragment<wmma::matrix_b, 16, 16, 16, bf16, wmma::col_major> bb;
                wmma::load_matrix_sync(bb, Ss + (tcb + j) * 16 * 80 + k * 16, 80);
                wmma::mma_sync(acc[j], ah, bb, acc[j]);
                wmma::mma_sync(acc[j], al, bb, acc[j]);
            }
        }
        __syncthreads();  // all Ss reads done before Sc overwrite
        wmma::store_matrix_sync(Sc + tm * 16 * 68 + (tcb + 0) * 16, acc[0], 68, wmma::mem_row_major);
        wmma::store_matrix_sync(Sc + tm * 16 * 68 + (tcb + 1) * 16, acc[1], 68, wmma::mem_row_major);
        __syncthreads();

        if (tid < 64) {   // running top-2 (ascending index scan => lowest-index tie-break)
            int base = c * 64;
#pragma unroll 4
            for (int cc = 0; cc < 64; cc++) {
                float s = Sc[tid * 68 + cc];
                if (s > v1) { v2 = v1; i2 = i1; v1 = s; i1 = base + cc; }
                else if (s > v2) { v2 = s; i2 = base + cc; }
            }
        }
    }
    __syncthreads();

    if (tid < 64) {
        float t = temp[0];
        float inv = 1.0f / (t * 8.0f);           // 1/(temperature*sqrt(64))
        float e = expf((v2 - v1) * inv);
        float w1 = 1.0f / (1.0f + e);
        w1s[tid] = w1;
        w2s[tid] = 1.0f - w1;
        i1s[tid] = i1;
        i2s[tid] = i2;
    }
    __syncthreads();

    {   // gather slot values, blend, write bf16 read
        int tt = tid >> 2, p = tid & 3;
        const float* V = vals + (size_t)h * NS * SD;
        const float4* r1 = (const float4*)(V + (size_t)i1s[tt] * SD);
        const float4* r2 = (const float4*)(V + (size_t)i2s[tt] * SD);
        float a = w1s[tt], b = w2s[tt];
        bf16* dst = g_read + (size_t)(m0 + tt) * DM + h * SD + p * 16;
#pragma unroll
        for (int j = 0; j < 4; j++) {
            float4 xa = r1[p * 4 + j], xb = r2[p * 4 + j];
            float f0 = a * xa.x + b * xb.x;
            float f1 = a * xa.y + b * xb.y;
            float f2 = a * xa.z + b * xb.z;
            float f3 = a * xa.w + b * xb.w;
            ((__nv_bfloat162*)(dst + j * 4))[0] = __floats2bfloat162_rn(f0, f1);
            ((__nv_bfloat162*)(dst + j * 4))[1] = __floats2bfloat162_rn(f2, f3);
        }
    }
}

// ---------------- out projection: out = read @ out_w^T + out_b + x ----------
__global__ void __launch_bounds__(256) gemm_out(const float* __restrict__ ob,
                                                const float* __restrict__ x,
                                                float* __restrict__ out) {
    __shared__ __align__(16) bf16 As[128 * 40];
    __shared__ __align__(16) bf16 Ws[64 * 40];
    __shared__ __align__(16) float Cs[8 * 16 * 20];

    int tid = threadIdx.x, warp = tid >> 5, lane = tid & 31;
    int m0 = blockIdx.y * 128, n0 = blockIdx.x * 64;
    int wm = warp & 3, wn = warp >> 2;

    wmma::fragment<wmma::accumulator, 16, 16, 16, float> acc[2][2];
#pragma unroll
    for (int i = 0; i < 2; i++)
#pragma unroll
        for (int j = 0; j < 2; j++) wmma::fill_fragment(acc[i][j], 0.0f);

    int rA = tid >> 2, cv = tid & 3;
    for (int k0 = 0; k0 < DM; k0 += 32) {
        size_t a0 = (size_t)(m0 + rA) * DM + k0 + cv * 8;
        size_t a1 = (size_t)(m0 + rA + 64) * DM + k0 + cv * 8;
        ((uint4*)(As + rA * 40))[cv] = *(const uint4*)(g_read + a0);
        ((uint4*)(As + (rA + 64) * 40))[cv] = *(const uint4*)(g_read + a1);
        size_t w0 = (size_t)(n0 + rA) * DM + k0 + cv * 8;
        ((uint4*)(Ws + rA * 40))[cv] = *(const uint4*)(g_wo + w0);
        __syncthreads();
#pragma unroll
        for (int ks = 0; ks < 2; ks++) {
            wmma::fragment<wmma::matrix_a, 16, 16, 16, bf16, wmma::row_major> af[2];
            wmma::fragment<wmma::matrix_b, 16, 16, 16, bf16, wmma::col_major> bf_[2];
#pragma unroll
            for (int i = 0; i < 2; i++)
                wmma::load_matrix_sync(af[i], As + (wm * 32 + i * 16) * 40 + ks * 16, 40);
#pragma unroll
            for (int j = 0; j < 2; j++)
                wmma::load_matrix_sync(bf_[j], Ws + (wn * 32 + j * 16) * 40 + ks * 16, 40);
#pragma unroll
            for (int i = 0; i < 2; i++)
#pragma unroll
                for (int j = 0; j < 2; j++)
                    wmma::mma_sync(acc[i][j], af[i], bf_[j], acc[i][j]);
        }
        __syncthreads();
    }
    float* cs = Cs + warp * (16 * 20);
#pragma unroll
    for (int i = 0; i < 2; i++)
#pragma unroll
        for (int j = 0; j < 2; j++) {
            wmma::store_matrix_sync(cs, acc[i][j], 20, wmma::mem_row_major);
            __syncwarp();
            int mb = m0 + wm * 32 + i * 16, nb = n0 + wn * 32 + j * 16;
#pragma unroll
            for (int t = 0; t < 8; t++) {
                int e = t * 32 + lane;
                int r = e >> 4, c = e & 15;
                size_t o = (size_t)(mb + r) * DM + nb + c;
                out[o] = cs[r * 20 + c] + ob[nb + c] + x[o];
            }
            __syncwarp();
        }
}

// ---------------- launch ----------------------------------------------------
extern "C" void kernel_launch(void* const* d_in, const int* in_sizes, int n_in,
                              void* d_out, int out_size) {
    const float* x = (const float*)d_in[0];
    const float* gamma = (const float*)d_in[1];
    const float* beta = (const float*)d_in[2];
    const float* qw = (const float*)d_in[3];
    const float* qb = (const float*)d_in[4];
    const float* sig = (const float*)d_in[5];
    const float* vals = (const float*)d_in[6];
    const float* ow = (const float*)d_in[7];
    const float* ob = (const float*)d_in[8];
    const float* temp = (const float*)d_in[9];
    float* out = (float*)d_out;

    convert_kernel<<<(3 * DM * DM) / 256, 256>>>(qw, ow, sig);
    ln_kernel<<<TOKENS, 256>>>(x, gamma, beta);
    gemm_qproj<<<dim3(DM / 64, TOKENS / 128), 256>>>(qb);
    scores_kernel<<<dim3(TOKENS / 64, NH), 256>>>(vals, temp);
    gemm_out<<<dim3(DM / 64, TOKENS / 128), 256>>>(ob, x, out);
}

// round 6
// speedup vs baseline: 1.3432x; 1.3395x over previous
#include <cuda_runtime.h>
#include <cuda_bf16.h>
#include <mma.h>
#include <cstdint>

using namespace nvcuda;
typedef __nv_bfloat16 bf16;
typedef unsigned int u32;

#define TOKENS 8192
#define DM 1024
#define NH 16
#define SD 64
#define NS 1024

// ---------------- scratch (static __device__, no allocation) ----------------
__device__ __align__(16) bf16 g_xh[TOKENS * DM];     // x_norm hi
__device__ __align__(16) bf16 g_xl[TOKENS * DM];     // x_norm lo
__device__ __align__(16) bf16 g_qh[TOKENS * DM];     // q hi
__device__ __align__(16) bf16 g_ql[TOKENS * DM];     // q lo
__device__ __align__(16) bf16 g_read[TOKENS * DM];   // routed read (bf16)
__device__ __align__(16) bf16 g_wqh[DM * DM];        // q_w hi
__device__ __align__(16) bf16 g_wql[DM * DM];        // q_w lo
__device__ __align__(16) bf16 g_wo[DM * DM];         // out_w (plain bf16)
__device__ __align__(16) bf16 g_sig[NH * NS * SD];   // ternarized signatures

// ---------------- helpers ----------------------------------------------------
__device__ __forceinline__ void cp16(void* s, const void* g) {
    asm volatile("cp.async.cg.shared.global [%0], [%1], 16;\n"
                 :: "r"((u32)__cvta_generic_to_shared(s)), "l"(g));
}
__device__ __forceinline__ void cp_commit() { asm volatile("cp.async.commit_group;\n"); }
__device__ __forceinline__ void cp_wait0() { asm volatile("cp.async.wait_group 0;\n"); }

__device__ __forceinline__ void mma_bf16(float& c0, float& c1, float& c2, float& c3,
                                         u32 a0, u32 a1, u32 a2, u32 a3,
                                         u32 b0, u32 b1) {
    asm volatile(
        "mma.sync.aligned.m16n8k16.row.col.f32.bf16.bf16.f32 "
        "{%0,%1,%2,%3}, {%4,%5,%6,%7}, {%8,%9}, {%0,%1,%2,%3};\n"
        : "+f"(c0), "+f"(c1), "+f"(c2), "+f"(c3)
        : "r"(a0), "r"(a1), "r"(a2), "r"(a3), "r"(b0), "r"(b1));
}

// ---------------- convert weights / ternarize signatures --------------------
__global__ void __launch_bounds__(256) convert_kernel(const float* __restrict__ qw,
                                                      const float* __restrict__ ow,
                                                      const float* __restrict__ sig) {
    int i = blockIdx.x * 256 + threadIdx.x;
    const int N = DM * DM;
    if (i < N) {
        float w = qw[i];
        bf16 h = __float2bfloat16(w);
        g_wqh[i] = h;
        g_wql[i] = __float2bfloat16(w - __bfloat162float(h));
    } else if (i < 2 * N) {
        g_wo[i - N] = __float2bfloat16(ow[i - N]);
    } else if (i < 2 * N + NH * NS * SD) {
        float s = sig[i - 2 * N];
        float t = (s > 0.3f) ? 1.0f : ((s < -0.3f) ? -1.0f : 0.0f);
        g_sig[i - 2 * N] = __float2bfloat16(t);
    }
}

// ---------------- layernorm with hi/lo split output -------------------------
__global__ void __launch_bounds__(256) ln_kernel(const float* __restrict__ x,
                                                 const float* __restrict__ gamma,
                                                 const float* __restrict__ beta) {
    int m = blockIdx.x;
    int tid = threadIdx.x;
    const float4 v = reinterpret_cast<const float4*>(x + (size_t)m * DM)[tid];
    float s = v.x + v.y + v.z + v.w;
    float q = v.x * v.x + v.y * v.y + v.z * v.z + v.w * v.w;
#pragma unroll
    for (int o = 16; o; o >>= 1) {
        s += __shfl_xor_sync(0xffffffffu, s, o);
        q += __shfl_xor_sync(0xffffffffu, q, o);
    }
    __shared__ float ss[8], qq[8];
    int w = tid >> 5;
    if ((tid & 31) == 0) { ss[w] = s; qq[w] = q; }
    __syncthreads();
    if (tid == 0) {
        float S = 0.f, Q = 0.f;
        for (int i = 0; i < 8; i++) { S += ss[i]; Q += qq[i]; }
        ss[0] = S; qq[0] = Q;
    }
    __syncthreads();
    float mean = ss[0] * (1.0f / DM);
    float var = qq[0] * (1.0f / DM) - mean * mean;
    float r = rsqrtf(var + 1e-5f);
    const float4 g = reinterpret_cast<const float4*>(gamma)[tid];
    const float4 b = reinterpret_cast<const float4*>(beta)[tid];
    float o0 = (v.x - mean) * r * g.x + b.x;
    float o1 = (v.y - mean) * r * g.y + b.y;
    float o2 = (v.z - mean) * r * g.z + b.z;
    float o3 = (v.w - mean) * r * g.w + b.w;
    size_t base = (size_t)m * DM + tid * 4;
    float oo[4] = {o0, o1, o2, o3};
#pragma unroll
    for (int i = 0; i < 4; i++) {
        bf16 h = __float2bfloat16(oo[i]);
        g_xh[base + i] = h;
        g_xl[base + i] = __float2bfloat16(oo[i] - __bfloat162float(h));
    }
}

// ---------------- split-bf16 q projection: q = xn @ q_w^T + q_b -------------
__global__ void __launch_bounds__(256) gemm_qproj(const float* __restrict__ qb) {
    __shared__ __align__(16) bf16 Ah[128 * 40];
    __shared__ __align__(16) bf16 Al[128 * 40];
    __shared__ __align__(16) bf16 Wh[64 * 40];
    __shared__ __align__(16) bf16 Wl[64 * 40];
    __shared__ __align__(16) float Cs[8 * 16 * 20];

    int tid = threadIdx.x, warp = tid >> 5, lane = tid & 31;
    int m0 = blockIdx.y * 128, n0 = blockIdx.x * 64;
    int wm = warp & 3, wn = warp >> 2;

    wmma::fragment<wmma::accumulator, 16, 16, 16, float> acc[2][2];
#pragma unroll
    for (int i = 0; i < 2; i++)
#pragma unroll
        for (int j = 0; j < 2; j++) wmma::fill_fragment(acc[i][j], 0.0f);

    int rA = tid >> 2, cv = tid & 3;
    for (int k0 = 0; k0 < DM; k0 += 32) {
        size_t a0 = (size_t)(m0 + rA) * DM + k0 + cv * 8;
        size_t a1 = (size_t)(m0 + rA + 64) * DM + k0 + cv * 8;
        ((uint4*)(Ah + rA * 40))[cv] = *(const uint4*)(g_xh + a0);
        ((uint4*)(Ah + (rA + 64) * 40))[cv] = *(const uint4*)(g_xh + a1);
        ((uint4*)(Al + rA * 40))[cv] = *(const uint4*)(g_xl + a0);
        ((uint4*)(Al + (rA + 64) * 40))[cv] = *(const uint4*)(g_xl + a1);
        size_t w0 = (size_t)(n0 + rA) * DM + k0 + cv * 8;
        ((uint4*)(Wh + rA * 40))[cv] = *(const uint4*)(g_wqh + w0);
        ((uint4*)(Wl + rA * 40))[cv] = *(const uint4*)(g_wql + w0);
        __syncthreads();
#pragma unroll
        for (int ks = 0; ks < 2; ks++) {
            wmma::fragment<wmma::matrix_a, 16, 16, 16, bf16, wmma::row_major> ah[2], al[2];
            wmma::fragment<wmma::matrix_b, 16, 16, 16, bf16, wmma::col_major> bh[2], bl[2];
#pragma unroll
            for (int i = 0; i < 2; i++) {
                wmma::load_matrix_sync(ah[i], Ah + (wm * 32 + i * 16) * 40 + ks * 16, 40);
                wmma::load_matrix_sync(al[i], Al + (wm * 32 + i * 16) * 40 + ks * 16, 40);
            }
#pragma unroll
            for (int j = 0; j < 2; j++) {
                wmma::load_matrix_sync(bh[j], Wh + (wn * 32 + j * 16) * 40 + ks * 16, 40);
                wmma::load_matrix_sync(bl[j], Wl + (wn * 32 + j * 16) * 40 + ks * 16, 40);
            }
#pragma unroll
            for (int i = 0; i < 2; i++)
#pragma unroll
                for (int j = 0; j < 2; j++) {
                    wmma::mma_sync(acc[i][j], ah[i], bh[j], acc[i][j]);
                    wmma::mma_sync(acc[i][j], ah[i], bl[j], acc[i][j]);
                    wmma::mma_sync(acc[i][j], al[i], bh[j], acc[i][j]);
                }
        }
        __syncthreads();
    }
    float* cs = Cs + warp * (16 * 20);
#pragma unroll
    for (int i = 0; i < 2; i++)
#pragma unroll
        for (int j = 0; j < 2; j++) {
            wmma::store_matrix_sync(cs, acc[i][j], 20, wmma::mem_row_major);
            __syncwarp();
            int mb = m0 + wm * 32 + i * 16, nb = n0 + wn * 32 + j * 16;
#pragma unroll
            for (int t = 0; t < 8; t++) {
                int e = t * 32 + lane;
                int r = e >> 4, c = e & 15;
                float val = cs[r * 20 + c] + qb[nb + c];
                bf16 h = __float2bfloat16(val);
                size_t o = (size_t)(mb + r) * DM + nb + c;
                g_qh[o] = h;
                g_ql[o] = __float2bfloat16(val - __bfloat162float(h));
            }
            __syncwarp();
        }
}

// ---------------- fused scores + top-2 + softmax + gather (v2) --------------
// grid (128 token-tiles, 16 heads), 256 threads. Register-resident top-2,
// hoisted Q fragments, cp.async double-buffered signature chunks.
#define SLDS 72

#define TOP2(r, s, ix) do {                                   \
    bool _g1 = (s) > v1[r]; bool _g2 = (s) > v2[r];           \
    v2[r] = _g1 ? v1[r] : (_g2 ? (s) : v2[r]);                \
    i2[r] = _g1 ? i1[r] : (_g2 ? (ix) : i2[r]);               \
    v1[r] = _g1 ? (s) : v1[r];                                \
    i1[r] = _g1 ? (ix) : i1[r];                               \
} while (0)

__global__ void __launch_bounds__(256) scores_kernel(const float* __restrict__ vals,
                                                     const float* __restrict__ temp) {
    __shared__ __align__(16) bf16 SIG[2][64][SLDS];
    __shared__ float Mv1[2][64], Mv2[2][64];
    __shared__ int Mi1[2][64], Mi2[2][64];
    __shared__ float w1s[64], w2s[64];
    __shared__ int i1s[64], i2s[64];

    int tid = threadIdx.x, lane = tid & 31, warp = tid >> 5;
    int tm = warp & 3, tn = warp >> 2;
    int m0 = blockIdx.x * 64, h = blockIdx.y;
    int gid = lane >> 2, tig = lane & 3;

    // hoisted Q A-fragments (hi + lo), loaded straight from gmem
    u32 ah[4][4], al[4][4];
    {
        size_t r0 = (size_t)(m0 + tm * 16 + gid) * DM + h * SD + tig * 2;
        size_t r1 = r0 + 8 * DM;
#pragma unroll
        for (int ks = 0; ks < 4; ks++) {
            ah[ks][0] = *(const u32*)(g_qh + r0 + ks * 16);
            ah[ks][1] = *(const u32*)(g_qh + r1 + ks * 16);
            ah[ks][2] = *(const u32*)(g_qh + r0 + ks * 16 + 8);
            ah[ks][3] = *(const u32*)(g_qh + r1 + ks * 16 + 8);
            al[ks][0] = *(const u32*)(g_ql + r0 + ks * 16);
            al[ks][1] = *(const u32*)(g_ql + r1 + ks * 16);
            al[ks][2] = *(const u32*)(g_ql + r0 + ks * 16 + 8);
            al[ks][3] = *(const u32*)(g_ql + r1 + ks * 16 + 8);
        }
    }

    const bf16* sgbase = g_sig + (size_t)h * NS * SD;
    // stage chunk 0
    {
        int e0 = tid, e1 = tid + 256;
        cp16(&SIG[0][e0 >> 3][(e0 & 7) * 8], sgbase + (size_t)(e0 >> 3) * SD + (e0 & 7) * 8);
        cp16(&SIG[0][e1 >> 3][(e1 & 7) * 8], sgbase + (size_t)(e1 >> 3) * SD + (e1 & 7) * 8);
        cp_commit();
    }

    float v1[2] = {-1e30f, -1e30f}, v2[2] = {-1e30f, -1e30f};
    int i1[2] = {0, 0}, i2[2] = {0, 0};

    for (int c = 0; c < 16; c++) {
        int buf = c & 1;
        cp_wait0();
        __syncthreads();
        if (c < 15) {
            const bf16* src = sgbase + (size_t)(c + 1) * 64 * SD;
            int e0 = tid, e1 = tid + 256;
            cp16(&SIG[buf ^ 1][e0 >> 3][(e0 & 7) * 8], src + (size_t)(e0 >> 3) * SD + (e0 & 7) * 8);
            cp16(&SIG[buf ^ 1][e1 >> 3][(e1 & 7) * 8], src + (size_t)(e1 >> 3) * SD + (e1 & 7) * 8);
            cp_commit();
        }
        int cbase = c * 64 + tn * 32 + tig * 2;
#pragma unroll
        for (int nt = 0; nt < 4; nt++) {
            float c0 = 0.f, c1 = 0.f, c2 = 0.f, c3 = 0.f;
            const bf16* bp = &SIG[buf][tn * 32 + nt * 8 + gid][tig * 2];
#pragma unroll
            for (int ks = 0; ks < 4; ks++) {
                u32 b0 = *(const u32*)(bp + ks * 16);
                u32 b1 = *(const u32*)(bp + ks * 16 + 8);
                mma_bf16(c0, c1, c2, c3, ah[ks][0], ah[ks][1], ah[ks][2], ah[ks][3], b0, b1);
                mma_bf16(c0, c1, c2, c3, al[ks][0], al[ks][1], al[ks][2], al[ks][3], b0, b1);
            }
            int idx = cbase + nt * 8;
            TOP2(0, c0, idx); TOP2(0, c1, idx + 1);
            TOP2(1, c2, idx); TOP2(1, c3, idx + 1);
        }
    }

    // merge top-2 across the 4 lanes sharing each row (tig axis)
#pragma unroll
    for (int off = 1; off < 4; off <<= 1) {
#pragma unroll
        for (int r = 0; r < 2; r++) {
            float ov1 = __shfl_xor_sync(0xffffffffu, v1[r], off);
            float ov2 = __shfl_xor_sync(0xffffffffu, v2[r], off);
            int oi1 = __shfl_xor_sync(0xffffffffu, i1[r], off);
            int oi2 = __shfl_xor_sync(0xffffffffu, i2[r], off);
            bool t = ov1 > v1[r];
            float lc = t ? v1[r] : ov1; int lci = t ? i1[r] : oi1;
            float s2 = t ? ov2 : v2[r]; int si2 = t ? oi2 : i2[r];
            v1[r] = t ? ov1 : v1[r];    i1[r] = t ? oi1 : i1[r];
            bool u = lc > s2;
            v2[r] = u ? lc : s2;        i2[r] = u ? lci : si2;
        }
    }
    if (tig == 0) {
        int r = tm * 16 + gid;
        Mv1[tn][r] = v1[0]; Mv2[tn][r] = v2[0]; Mi1[tn][r] = i1[0]; Mi2[tn][r] = i2[0];
        Mv1[tn][r + 8] = v1[1]; Mv2[tn][r + 8] = v2[1]; Mi1[tn][r + 8] = i1[1]; Mi2[tn][r + 8] = i2[1];
    }
    __syncthreads();

    if (tid < 64) {
        float a1 = Mv1[0][tid], a2 = Mv2[0][tid];
        int ja1 = Mi1[0][tid], ja2 = Mi2[0][tid];
        float b1 = Mv1[1][tid], b2 = Mv2[1][tid];
        int jb1 = Mi1[1][tid], jb2 = Mi2[1][tid];
        float V1, V2; int I1, I2;
        if (a1 >= b1) {
            V1 = a1; I1 = ja1;
            bool u = b1 > a2; V2 = u ? b1 : a2; I2 = u ? jb1 : ja2;
        } else {
            V1 = b1; I1 = jb1;
            bool u = a1 > b2; V2 = u ? a1 : b2; I2 = u ? ja1 : jb2;
        }
        float t = temp[0];
        float inv = 1.0f / (t * 8.0f);           // 1/(temperature*sqrt(64))
        float e = expf((V2 - V1) * inv);
        float w1 = 1.0f / (1.0f + e);
        w1s[tid] = w1;
        w2s[tid] = 1.0f - w1;
        i1s[tid] = I1;
        i2s[tid] = I2;
    }
    __syncthreads();

    {   // gather slot values, blend, write bf16 read
        int tt = tid >> 2, p = tid & 3;
        const float* V = vals + (size_t)h * NS * SD;
        const float4* r1 = (const float4*)(V + (size_t)i1s[tt] * SD);
        const float4* r2 = (const float4*)(V + (size_t)i2s[tt] * SD);
        float a = w1s[tt], b = w2s[tt];
        bf16* dst = g_read + (size_t)(m0 + tt) * DM + h * SD + p * 16;
#pragma unroll
        for (int j = 0; j < 4; j++) {
            float4 xa = r1[p * 4 + j], xb = r2[p * 4 + j];
            float f0 = a * xa.x + b * xb.x;
            float f1 = a * xa.y + b * xb.y;
            float f2 = a * xa.z + b * xb.z;
            float f3 = a * xa.w + b * xb.w;
            ((__nv_bfloat162*)(dst + j * 4))[0] = __floats2bfloat162_rn(f0, f1);
            ((__nv_bfloat162*)(dst + j * 4))[1] = __floats2bfloat162_rn(f2, f3);
        }
    }
}

// ---------------- out projection: out = read @ out_w^T + out_b + x ----------
__global__ void __launch_bounds__(256) gemm_out(const float* __restrict__ ob,
                                                const float* __restrict__ x,
                                                float* __restrict__ out) {
    __shared__ __align__(16) bf16 As[128 * 40];
    __shared__ __align__(16) bf16 Ws[64 * 40];
    __shared__ __align__(16) float Cs[8 * 16 * 20];

    int tid = threadIdx.x, warp = tid >> 5, lane = tid & 31;
    int m0 = blockIdx.y * 128, n0 = blockIdx.x * 64;
    int wm = warp & 3, wn = warp >> 2;

    wmma::fragment<wmma::accumulator, 16, 16, 16, float> acc[2][2];
#pragma unroll
    for (int i = 0; i < 2; i++)
#pragma unroll
        for (int j = 0; j < 2; j++) wmma::fill_fragment(acc[i][j], 0.0f);

    int rA = tid >> 2, cv = tid & 3;
    for (int k0 = 0; k0 < DM; k0 += 32) {
        size_t a0 = (size_t)(m0 + rA) * DM + k0 + cv * 8;
        size_t a1 = (size_t)(m0 + rA + 64) * DM + k0 + cv * 8;
        ((uint4*)(As + rA * 40))[cv] = *(const uint4*)(g_read + a0);
        ((uint4*)(As + (rA + 64) * 40))[cv] = *(const uint4*)(g_read + a1);
        size_t w0 = (size_t)(n0 + rA) * DM + k0 + cv * 8;
        ((uint4*)(Ws + rA * 40))[cv] = *(const uint4*)(g_wo + w0);
        __syncthreads();
#pragma unroll
        for (int ks = 0; ks < 2; ks++) {
            wmma::fragment<wmma::matrix_a, 16, 16, 16, bf16, wmma::row_major> af[2];
            wmma::fragment<wmma::matrix_b, 16, 16, 16, bf16, wmma::col_major> bf_[2];
#pragma unroll
            for (int i = 0; i < 2; i++)
                wmma::load_matrix_sync(af[i], As + (wm * 32 + i * 16) * 40 + ks * 16, 40);
#pragma unroll
            for (int j = 0; j < 2; j++)
                wmma::load_matrix_sync(bf_[j], Ws + (wn * 32 + j * 16) * 40 + ks * 16, 40);
#pragma unroll
            for (int i = 0; i < 2; i++)
#pragma unroll
                for (int j = 0; j < 2; j++)
                    wmma::mma_sync(acc[i][j], af[i], bf_[j], acc[i][j]);
        }
        __syncthreads();
    }
    float* cs = Cs + warp * (16 * 20);
#pragma unroll
    for (int i = 0; i < 2; i++)
#pragma unroll
        for (int j = 0; j < 2; j++) {
            wmma::store_matrix_sync(cs, acc[i][j], 20, wmma::mem_row_major);
            __syncwarp();
            int mb = m0 + wm * 32 + i * 16, nb = n0 + wn * 32 + j * 16;
#pragma unroll
            for (int t = 0; t < 8; t++) {
                int e = t * 32 + lane;
                int r = e >> 4, c = e & 15;
                size_t o = (size_t)(mb + r) * DM + nb + c;
                out[o] = cs[r * 20 + c] + ob[nb + c] + x[o];
            }
            __syncwarp();
        }
}

// ---------------- launch ----------------------------------------------------
extern "C" void kernel_launch(void* const* d_in, const int* in_sizes, int n_in,
                              void* d_out, int out_size) {
    const float* x = (const float*)d_in[0];
    const float* gamma = (const float*)d_in[1];
    const float* beta = (const float*)d_in[2];
    const float* qw = (const float*)d_in[3];
    const float* qb = (const float*)d_in[4];
    const float* sig = (const float*)d_in[5];
    const float* vals = (const float*)d_in[6];
    const float* ow = (const float*)d_in[7];
    const float* ob = (const float*)d_in[8];
    const float* temp = (const float*)d_in[9];
    float* out = (float*)d_out;

    convert_kernel<<<(3 * DM * DM) / 256, 256>>>(qw, ow, sig);
    ln_kernel<<<TOKENS, 256>>>(x, gamma, beta);
    gemm_qproj<<<dim3(DM / 64, TOKENS / 128), 256>>>(qb);
    scores_kernel<<<dim3(TOKENS / 64, NH), 256>>>(vals, temp);
    gemm_out<<<dim3(DM / 64, TOKENS / 128), 256>>>(ob, x, out);
}

// round 7
// speedup vs baseline: 1.5586x; 1.1603x over previous
#include <cuda_runtime.h>
#include <cuda_bf16.h>
#include <mma.h>
#include <cstdint>

using namespace nvcuda;
typedef __nv_bfloat16 bf16;
typedef unsigned int u32;

#define TOKENS 8192
#define DM 1024
#define NH 16
#define SD 64
#define NS 1024

// ---------------- scratch (static __device__, no allocation) ----------------
__device__ __align__(16) bf16 g_xh[TOKENS * DM];     // x_norm hi
__device__ __align__(16) bf16 g_xl[TOKENS * DM];     // x_norm lo
__device__ __align__(16) bf16 g_qh[TOKENS * DM];     // q hi
__device__ __align__(16) bf16 g_ql[TOKENS * DM];     // q lo
__device__ __align__(16) bf16 g_read[TOKENS * DM];   // routed read (bf16)
__device__ __align__(16) bf16 g_wqh[DM * DM];        // q_w hi
__device__ __align__(16) bf16 g_wql[DM * DM];        // q_w lo
__device__ __align__(16) bf16 g_wo[DM * DM];         // out_w (plain bf16)
__device__ __align__(16) bf16 g_sig[NH * NS * SD];   // ternarized signatures

// ---------------- helpers ----------------------------------------------------
__device__ __forceinline__ void cp16(void* s, const void* g) {
    asm volatile("cp.async.cg.shared.global [%0], [%1], 16;\n"
                 :: "r"((u32)__cvta_generic_to_shared(s)), "l"(g));
}
__device__ __forceinline__ void cp_commit() { asm volatile("cp.async.commit_group;\n"); }
__device__ __forceinline__ void cp_wait0() { asm volatile("cp.async.wait_group 0;\n"); }

__device__ __forceinline__ void mma_bf16(float& c0, float& c1, float& c2, float& c3,
                                         u32 a0, u32 a1, u32 a2, u32 a3,
                                         u32 b0, u32 b1) {
    asm volatile(
        "mma.sync.aligned.m16n8k16.row.col.f32.bf16.bf16.f32 "
        "{%0,%1,%2,%3}, {%4,%5,%6,%7}, {%8,%9}, {%0,%1,%2,%3};\n"
        : "+f"(c0), "+f"(c1), "+f"(c2), "+f"(c3)
        : "r"(a0), "r"(a1), "r"(a2), "r"(a3), "r"(b0), "r"(b1));
}

// order-preserving fp32 -> u32 key transform
__device__ __forceinline__ u32 fkey(float f) {
    u32 b = __float_as_uint(f);
    return b ^ (u32)(((int)b >> 31) | 0x80000000);
}
__device__ __forceinline__ float unkey(u32 u) {
    u32 b = (u & 0x80000000u) ? (u ^ 0x80000000u) : ~u;
    return __uint_as_float(b);
}

// ---------------- convert weights / ternarize signatures --------------------
__global__ void __launch_bounds__(256) convert_kernel(const float* __restrict__ qw,
                                                      const float* __restrict__ ow,
                                                      const float* __restrict__ sig) {
    int i = blockIdx.x * 256 + threadIdx.x;
    const int N = DM * DM;
    if (i < N) {
        float w = qw[i];
        bf16 h = __float2bfloat16(w);
        g_wqh[i] = h;
        g_wql[i] = __float2bfloat16(w - __bfloat162float(h));
    } else if (i < 2 * N) {
        g_wo[i - N] = __float2bfloat16(ow[i - N]);
    } else if (i < 2 * N + NH * NS * SD) {
        float s = sig[i - 2 * N];
        float t = (s > 0.3f) ? 1.0f : ((s < -0.3f) ? -1.0f : 0.0f);
        g_sig[i - 2 * N] = __float2bfloat16(t);
    }
}

// ---------------- layernorm with hi/lo split output -------------------------
__global__ void __launch_bounds__(256) ln_kernel(const float* __restrict__ x,
                                                 const float* __restrict__ gamma,
                                                 const float* __restrict__ beta) {
    int m = blockIdx.x;
    int tid = threadIdx.x;
    const float4 v = reinterpret_cast<const float4*>(x + (size_t)m * DM)[tid];
    float s = v.x + v.y + v.z + v.w;
    float q = v.x * v.x + v.y * v.y + v.z * v.z + v.w * v.w;
#pragma unroll
    for (int o = 16; o; o >>= 1) {
        s += __shfl_xor_sync(0xffffffffu, s, o);
        q += __shfl_xor_sync(0xffffffffu, q, o);
    }
    __shared__ float ss[8], qq[8];
    int w = tid >> 5;
    if ((tid & 31) == 0) { ss[w] = s; qq[w] = q; }
    __syncthreads();
    if (tid == 0) {
        float S = 0.f, Q = 0.f;
        for (int i = 0; i < 8; i++) { S += ss[i]; Q += qq[i]; }
        ss[0] = S; qq[0] = Q;
    }
    __syncthreads();
    float mean = ss[0] * (1.0f / DM);
    float var = qq[0] * (1.0f / DM) - mean * mean;
    float r = rsqrtf(var + 1e-5f);
    const float4 g = reinterpret_cast<const float4*>(gamma)[tid];
    const float4 b = reinterpret_cast<const float4*>(beta)[tid];
    float o0 = (v.x - mean) * r * g.x + b.x;
    float o1 = (v.y - mean) * r * g.y + b.y;
    float o2 = (v.z - mean) * r * g.z + b.z;
    float o3 = (v.w - mean) * r * g.w + b.w;
    size_t base = (size_t)m * DM + tid * 4;
    float oo[4] = {o0, o1, o2, o3};
#pragma unroll
    for (int i = 0; i < 4; i++) {
        bf16 h = __float2bfloat16(oo[i]);
        g_xh[base + i] = h;
        g_xl[base + i] = __float2bfloat16(oo[i] - __bfloat162float(h));
    }
}

// ---------------- split-bf16 q projection (cp.async double-buffered) --------
// dynamic smem: Ah[2][128*40] Al[2][128*40] Wh[2][64*40] Wl[2][64*40] Cs[8*16*20]
#define QP_SMEM (2*128*40*2*2 + 2*64*40*2*2 + 8*16*20*4)

__global__ void __launch_bounds__(256) gemm_qproj(const float* __restrict__ qb) {
    extern __shared__ char dyn[];
    bf16* Ah = (bf16*)dyn;                 // [2][5120]
    bf16* Al = Ah + 2 * 5120;              // [2][5120]
    bf16* Wh = Al + 2 * 5120;              // [2][2560]
    bf16* Wl = Wh + 2 * 2560;              // [2][2560]
    float* Cs = (float*)(Wl + 2 * 2560);   // [8*16*20]

    int tid = threadIdx.x, warp = tid >> 5, lane = tid & 31;
    int m0 = blockIdx.y * 128, n0 = blockIdx.x * 64;
    int wm = warp & 3, wn = warp >> 2;

    wmma::fragment<wmma::accumulator, 16, 16, 16, float> acc[2][2];
#pragma unroll
    for (int i = 0; i < 2; i++)
#pragma unroll
        for (int j = 0; j < 2; j++) wmma::fill_fragment(acc[i][j], 0.0f);

    // loader lambda-ish (macro): stage s, k-offset kb
    int rA0 = tid >> 2, rA1 = (tid + 256) >> 2, vA = tid & 3;
#define QP_STAGE(s, kb) do {                                                       \
        size_t a0 = (size_t)(m0 + rA0) * DM + (kb) + vA * 8;                       \
        size_t a1 = (size_t)(m0 + rA1) * DM + (kb) + vA * 8;                       \
        cp16(Ah + (s) * 5120 + rA0 * 40 + vA * 8, g_xh + a0);                      \
        cp16(Ah + (s) * 5120 + rA1 * 40 + vA * 8, g_xh + a1);                      \
        cp16(Al + (s) * 5120 + rA0 * 40 + vA * 8, g_xl + a0);                      \
        cp16(Al + (s) * 5120 + rA1 * 40 + vA * 8, g_xl + a1);                      \
        size_t w0 = (size_t)(n0 + rA0) * DM + (kb) + vA * 8;                       \
        cp16(Wh + (s) * 2560 + rA0 * 40 + vA * 8, g_wqh + w0);                     \
        cp16(Wl + (s) * 2560 + rA0 * 40 + vA * 8, g_wql + w0);                     \
    } while (0)

    QP_STAGE(0, 0);
    cp_commit();

    for (int kt = 0; kt < 32; kt++) {
        int buf = kt & 1;
        cp_wait0();
        __syncthreads();
        if (kt < 31) {
            QP_STAGE(buf ^ 1, (kt + 1) * 32);
            cp_commit();
        }
        bf16* ah_ = Ah + buf * 5120;
        bf16* al_ = Al + buf * 5120;
        bf16* wh_ = Wh + buf * 2560;
        bf16* wl_ = Wl + buf * 2560;
#pragma unroll
        for (int ks = 0; ks < 2; ks++) {
            wmma::fragment<wmma::matrix_a, 16, 16, 16, bf16, wmma::row_major> fah[2], fal[2];
            wmma::fragment<wmma::matrix_b, 16, 16, 16, bf16, wmma::col_major> fbh[2], fbl[2];
#pragma unroll
            for (int i = 0; i < 2; i++) {
                wmma::load_matrix_sync(fah[i], ah_ + (wm * 32 + i * 16) * 40 + ks * 16, 40);
                wmma::load_matrix_sync(fal[i], al_ + (wm * 32 + i * 16) * 40 + ks * 16, 40);
            }
#pragma unroll
            for (int j = 0; j < 2; j++) {
                wmma::load_matrix_sync(fbh[j], wh_ + (wn * 32 + j * 16) * 40 + ks * 16, 40);
                wmma::load_matrix_sync(fbl[j], wl_ + (wn * 32 + j * 16) * 40 + ks * 16, 40);
            }
#pragma unroll
            for (int i = 0; i < 2; i++)
#pragma unroll
                for (int j = 0; j < 2; j++) {
                    wmma::mma_sync(acc[i][j], fah[i], fbh[j], acc[i][j]);
                    wmma::mma_sync(acc[i][j], fah[i], fbl[j], acc[i][j]);
                    wmma::mma_sync(acc[i][j], fal[i], fbh[j], acc[i][j]);
                }
        }
    }
    __syncthreads();
    // epilogue: fp32 -> (hi, lo) bf16 pair
    float* cs = Cs + warp * (16 * 20);
#pragma unroll
    for (int i = 0; i < 2; i++)
#pragma unroll
        for (int j = 0; j < 2; j++) {
            wmma::store_matrix_sync(cs, acc[i][j], 20, wmma::mem_row_major);
            __syncwarp();
            int mb = m0 + wm * 32 + i * 16, nb = n0 + wn * 32 + j * 16;
#pragma unroll
            for (int t = 0; t < 8; t++) {
                int e = t * 32 + lane;
                int r = e >> 4, c = e & 15;
                float val = cs[r * 20 + c] + qb[nb + c];
                bf16 h = __float2bfloat16(val);
                size_t o = (size_t)(mb + r) * DM + nb + c;
                g_qh[o] = h;
                g_ql[o] = __float2bfloat16(val - __bfloat162float(h));
            }
            __syncwarp();
        }
}

// ---------------- fused scores + top-2 + softmax + gather (v3) --------------
// Integer-key top-2 (order-preserving transform, idx packed in low 10 bits).
#define SLDS 72

__global__ void __launch_bounds__(256) scores_kernel(const float* __restrict__ vals,
                                                     const float* __restrict__ temp) {
    __shared__ __align__(16) bf16 SIG[2][64][SLDS];
    __shared__ u32 Mk1[2][64], Mk2[2][64];
    __shared__ float w1s[64], w2s[64];
    __shared__ int i1s[64], i2s[64];

    int tid = threadIdx.x, lane = tid & 31, warp = tid >> 5;
    int tm = warp & 3, tn = warp >> 2;
    int m0 = blockIdx.x * 64, h = blockIdx.y;
    int gid = lane >> 2, tig = lane & 3;

    // hoisted Q A-fragments (hi + lo), loaded straight from gmem
    u32 ah[4][4], al[4][4];
    {
        size_t r0 = (size_t)(m0 + tm * 16 + gid) * DM + h * SD + tig * 2;
        size_t r1 = r0 + 8 * DM;
#pragma unroll
        for (int ks = 0; ks < 4; ks++) {
            ah[ks][0] = *(const u32*)(g_qh + r0 + ks * 16);
            ah[ks][1] = *(const u32*)(g_qh + r1 + ks * 16);
            ah[ks][2] = *(const u32*)(g_qh + r0 + ks * 16 + 8);
            ah[ks][3] = *(const u32*)(g_qh + r1 + ks * 16 + 8);
            al[ks][0] = *(const u32*)(g_ql + r0 + ks * 16);
            al[ks][1] = *(const u32*)(g_ql + r1 + ks * 16);
            al[ks][2] = *(const u32*)(g_ql + r0 + ks * 16 + 8);
            al[ks][3] = *(const u32*)(g_ql + r1 + ks * 16 + 8);
        }
    }

    const bf16* sgbase = g_sig + (size_t)h * NS * SD;
    {
        int e0 = tid, e1 = tid + 256;
        cp16(&SIG[0][e0 >> 3][(e0 & 7) * 8], sgbase + (size_t)(e0 >> 3) * SD + (e0 & 7) * 8);
        cp16(&SIG[0][e1 >> 3][(e1 & 7) * 8], sgbase + (size_t)(e1 >> 3) * SD + (e1 & 7) * 8);
        cp_commit();
    }

    u32 k1[2] = {0u, 0u}, k2[2] = {0u, 0u};

#define UPD(r, f, ci) do {                                       \
        u32 _k = (fkey(f) & 0xFFFFFC00u) | (u32)(ci);            \
        u32 _m = min(k1[r], _k);                                 \
        k1[r] = max(k1[r], _k);                                  \
        k2[r] = max(k2[r], _m);                                  \
    } while (0)

    for (int c = 0; c < 16; c++) {
        int buf = c & 1;
        cp_wait0();
        __syncthreads();
        if (c < 15) {
            const bf16* src = sgbase + (size_t)(c + 1) * 64 * SD;
            int e0 = tid, e1 = tid + 256;
            cp16(&SIG[buf ^ 1][e0 >> 3][(e0 & 7) * 8], src + (size_t)(e0 >> 3) * SD + (e0 & 7) * 8);
            cp16(&SIG[buf ^ 1][e1 >> 3][(e1 & 7) * 8], src + (size_t)(e1 >> 3) * SD + (e1 & 7) * 8);
            cp_commit();
        }
        int cbase = c * 64 + tn * 32 + tig * 2;
#pragma unroll
        for (int nt = 0; nt < 4; nt++) {
            float c0 = 0.f, c1 = 0.f, c2 = 0.f, c3 = 0.f;
            const bf16* bp = &SIG[buf][tn * 32 + nt * 8 + gid][tig * 2];
#pragma unroll
            for (int ks = 0; ks < 4; ks++) {
                u32 b0 = *(const u32*)(bp + ks * 16);
                u32 b1 = *(const u32*)(bp + ks * 16 + 8);
                mma_bf16(c0, c1, c2, c3, ah[ks][0], ah[ks][1], ah[ks][2], ah[ks][3], b0, b1);
                mma_bf16(c0, c1, c2, c3, al[ks][0], al[ks][1], al[ks][2], al[ks][3], b0, b1);
            }
            int ci0 = 1023 - (cbase + nt * 8);  // for c0 (row gid) and c2 (row gid+8)
            UPD(0, c0, ci0); UPD(0, c1, ci0 - 1);
            UPD(1, c2, ci0); UPD(1, c3, ci0 - 1);
        }
    }

    // merge top-2 across the 4 lanes sharing each row (tig axis)
#pragma unroll
    for (int off = 1; off < 4; off <<= 1) {
#pragma unroll
        for (int r = 0; r < 2; r++) {
            u32 ok1 = __shfl_xor_sync(0xffffffffu, k1[r], off);
            u32 ok2 = __shfl_xor_sync(0xffffffffu, k2[r], off);
            u32 m = min(k1[r], ok1);
            k1[r] = max(k1[r], ok1);
            k2[r] = max(max(k2[r], ok2), m);
        }
    }
    if (tig == 0) {
        int r = tm * 16 + gid;
        Mk1[tn][r] = k1[0]; Mk2[tn][r] = k2[0];
        Mk1[tn][r + 8] = k1[1]; Mk2[tn][r + 8] = k2[1];
    }
    __syncthreads();

    if (tid < 64) {
        u32 a1 = Mk1[0][tid], a2 = Mk2[0][tid];
        u32 b1 = Mk1[1][tid], b2 = Mk2[1][tid];
        u32 m = min(a1, b1);
        u32 K1 = max(a1, b1);
        u32 K2 = max(max(a2, b2), m);
        int I1 = 1023 - (int)(K1 & 1023u);
        int I2 = 1023 - (int)(K2 & 1023u);
        float V1 = unkey(K1 & 0xFFFFFC00u);
        float V2 = unkey(K2 & 0xFFFFFC00u);
        float t = temp[0];
        float inv = 1.0f / (t * 8.0f);           // 1/(temperature*sqrt(64))
        float e = expf((V2 - V1) * inv);
        float w1 = 1.0f / (1.0f + e);
        w1s[tid] = w1;
        w2s[tid] = 1.0f - w1;
        i1s[tid] = I1;
        i2s[tid] = I2;
    }
    __syncthreads();

    {   // gather slot values, blend, write bf16 read
        int tt = tid >> 2, p = tid & 3;
        const float* V = vals + (size_t)h * NS * SD;
        const float4* r1 = (const float4*)(V + (size_t)i1s[tt] * SD);
        const float4* r2 = (const float4*)(V + (size_t)i2s[tt] * SD);
        float a = w1s[tt], b = w2s[tt];
        bf16* dst = g_read + (size_t)(m0 + tt) * DM + h * SD + p * 16;
#pragma unroll
        for (int j = 0; j < 4; j++) {
            float4 xa = r1[p * 4 + j], xb = r2[p * 4 + j];
            float f0 = a * xa.x + b * xb.x;
            float f1 = a * xa.y + b * xb.y;
            float f2 = a * xa.z + b * xb.z;
            float f3 = a * xa.w + b * xb.w;
            ((__nv_bfloat162*)(dst + j * 4))[0] = __floats2bfloat162_rn(f0, f1);
            ((__nv_bfloat162*)(dst + j * 4))[1] = __floats2bfloat162_rn(f2, f3);
        }
    }
}

// ---------------- out projection (cp.async double-buffered) -----------------
__global__ void __launch_bounds__(256) gemm_out(const float* __restrict__ ob,
                                                const float* __restrict__ x,
                                                float* __restrict__ out) {
    __shared__ __align__(16) bf16 As[2][128 * 40];
    __shared__ __align__(16) bf16 Ws[2][64 * 40];
    __shared__ __align__(16) float Cs[8 * 16 * 20];

    int tid = threadIdx.x, warp = tid >> 5, lane = tid & 31;
    int m0 = blockIdx.y * 128, n0 = blockIdx.x * 64;
    int wm = warp & 3, wn = warp >> 2;

    wmma::fragment<wmma::accumulator, 16, 16, 16, float> acc[2][2];
#pragma unroll
    for (int i = 0; i < 2; i++)
#pragma unroll
        for (int j = 0; j < 2; j++) wmma::fill_fragment(acc[i][j], 0.0f);

    int rA0 = tid >> 2, rA1 = (tid + 256) >> 2, vA = tid & 3;
#define GO_STAGE(s, kb) do {                                                   \
        size_t a0 = (size_t)(m0 + rA0) * DM + (kb) + vA * 8;                   \
        size_t a1 = (size_t)(m0 + rA1) * DM + (kb) + vA * 8;                   \
        cp16(&As[s][rA0 * 40 + vA * 8], g_read + a0);                          \
        cp16(&As[s][rA1 * 40 + vA * 8], g_read + a1);                          \
        size_t w0 = (size_t)(n0 + rA0) * DM + (kb) + vA * 8;                   \
        cp16(&Ws[s][rA0 * 40 + vA * 8], g_wo + w0);                            \
    } while (0)

    GO_STAGE(0, 0);
    cp_commit();

    for (int kt = 0; kt < 32; kt++) {
        int buf = kt & 1;
        cp_wait0();
        __syncthreads();
        if (kt < 31) {
            GO_STAGE(buf ^ 1, (kt + 1) * 32);
            cp_commit();
        }
#pragma unroll
        for (int ks = 0; ks < 2; ks++) {
            wmma::fragment<wmma::matrix_a, 16, 16, 16, bf16, wmma::row_major> af[2];
            wmma::fragment<wmma::matrix_b, 16, 16, 16, bf16, wmma::col_major> bf_[2];
#pragma unroll
            for (int i = 0; i < 2; i++)
                wmma::load_matrix_sync(af[i], &As[buf][(wm * 32 + i * 16) * 40 + ks * 16], 40);
#pragma unroll
            for (int j = 0; j < 2; j++)
                wmma::load_matrix_sync(bf_[j], &Ws[buf][(wn * 32 + j * 16) * 40 + ks * 16], 40);
#pragma unroll
            for (int i = 0; i < 2; i++)
#pragma unroll
                for (int j = 0; j < 2; j++)
                    wmma::mma_sync(acc[i][j], af[i], bf_[j], acc[i][j]);
        }
    }
    __syncthreads();
    float* cs = Cs + warp * (16 * 20);
#pragma unroll
    for (int i = 0; i < 2; i++)
#pragma unroll
        for (int j = 0; j < 2; j++) {
            wmma::store_matrix_sync(cs, acc[i][j], 20, wmma::mem_row_major);
            __syncwarp();
            int mb = m0 + wm * 32 + i * 16, nb = n0 + wn * 32 + j * 16;
#pragma unroll
            for (int t = 0; t < 8; t++) {
                int e = t * 32 + lane;
                int r = e >> 4, c = e & 15;
                size_t o = (size_t)(mb + r) * DM + nb + c;
                out[o] = cs[r * 20 + c] + ob[nb + c] + x[o];
            }
            __syncwarp();
        }
}

// ---------------- launch ----------------------------------------------------
extern "C" void kernel_launch(void* const* d_in, const int* in_sizes, int n_in,
                              void* d_out, int out_size) {
    const float* x = (const float*)d_in[0];
    const float* gamma = (const float*)d_in[1];
    const float* beta = (const float*)d_in[2];
    const float* qw = (const float*)d_in[3];
    const float* qb = (const float*)d_in[4];
    const float* sig = (const float*)d_in[5];
    const float* vals = (const float*)d_in[6];
    const float* ow = (const float*)d_in[7];
    const float* ob = (const float*)d_in[8];
    const float* temp = (const float*)d_in[9];
    float* out = (float*)d_out;

    cudaFuncSetAttribute(gemm_qproj, cudaFuncAttributeMaxDynamicSharedMemorySize, QP_SMEM);

    convert_kernel<<<(3 * DM * DM) / 256, 256>>>(qw, ow, sig);
    ln_kernel<<<TOKENS, 256>>>(x, gamma, beta);
    gemm_qproj<<<dim3(DM / 64, TOKENS / 128), 256, QP_SMEM>>>(qb);
    scores_kernel<<<dim3(TOKENS / 64, NH), 256>>>(vals, temp);
    gemm_out<<<dim3(DM / 64, TOKENS / 128), 256>>>(ob, x, out);
}